// round 4
// baseline (speedup 1.0000x reference)
#include <cuda_runtime.h>
#include <cstdint>

// ============================================================================
// LSTM cell, base sm_103 ISA. tf32 mma.sync m16n8k8, cp.async 4-stage,
// fragment-packed operands. CTA 256x256, warp 64x64 (reg-reuse to unload the
// SMEM crossbar, which bound the 256x128 version). Fused gate epilogue.
//
// z[4096, 8192] = A[4096, 4096] @ B[4096, 8192]
//   A = [x | h], B[k][4u+g] = W{x,h}{f,i,o,g}[k][u]  (gate-interleaved)
// ============================================================================

#define MTOT 4096
#define KTOT 4096
#define NTOT 8192
#define UDIM 2048

#define TM 256
#define TN 256
#define TK 16          // 2 k8 sub-steps per stage
#define STAGES 4
#define NTHREADS 512

#define MBTOT 256              // MTOT/16
#define NBTOT 1024             // NTOT/8

#define SA_STAGE 16384         // 2 k8 * 16 mb * 512 B
#define SB_STAGE 16384         // 2 k8 * 32 nb * 256 B
#define STAGE_BYTES (SA_STAGE + SB_STAGE)      // 32768
#define PIPE_BYTES (STAGES * STAGE_BYTES)      // 131072
#define ZLD 132
#define Z_BYTES (TM * ZLD * 4)                 // 135168 (one 128-col half)
#define SMEM_BYTES (Z_BYTES > PIPE_BYTES ? Z_BYTES : PIPE_BYTES)

// Fragment-packed tf32 operands.
// g_Ap[k8][mb][lane][4] : lane=(gq<<2)|kq holds A[mb*16+gq+{0,8}][k8*8+kq+{0,4}]
// g_Bp[k8][nb][lane][2] : lane=(nq<<2)|kq holds B[k8*8+kq+{0,4}][nb*8+nq]
static __device__ __align__(16) float g_Ap[(size_t)MTOT * KTOT];   // 64 MB
static __device__ __align__(16) float g_Bp[(size_t)KTOT * NTOT];   // 128 MB

// ---------------------------------------------------------------- helpers
__device__ __forceinline__ uint32_t smem_u32(const void* p) {
    uint32_t a;
    asm("{ .reg .u64 t; cvta.to.shared.u64 t, %1; cvt.u32.u64 %0, t; }"
        : "=r"(a) : "l"(p));
    return a;
}

__device__ __forceinline__ uint32_t tf32r(float v) {   // round-to-nearest tf32
    uint32_t r;
    asm("cvt.rna.tf32.f32 %0, %1;" : "=r"(r) : "f"(v));
    return r;
}

__device__ __forceinline__ void cp16(uint32_t dst, const void* src) {
    asm volatile("cp.async.cg.shared.global [%0], [%1], 16;"
                 :: "r"(dst), "l"(src) : "memory");
}
__device__ __forceinline__ void cp_commit() {
    asm volatile("cp.async.commit_group;" ::: "memory");
}
template <int N>
__device__ __forceinline__ void cp_wait() {
    asm volatile("cp.async.wait_group %0;" :: "n"(N) : "memory");
}

__device__ __forceinline__ void mma8(float* d, const uint32_t* a, const uint32_t* b) {
    asm volatile(
        "mma.sync.aligned.m16n8k8.row.col.f32.tf32.tf32.f32 "
        "{%0,%1,%2,%3}, {%4,%5,%6,%7}, {%8,%9}, {%0,%1,%2,%3};"
        : "+f"(d[0]), "+f"(d[1]), "+f"(d[2]), "+f"(d[3])
        : "r"(a[0]), "r"(a[1]), "r"(a[2]), "r"(a[3]), "r"(b[0]), "r"(b[1]));
}

// ---------------------------------------------------------------- prepasses
__global__ void __launch_bounds__(256) pack_A_kernel(
    const float* __restrict__ x, const float* __restrict__ h)
{
    uint32_t t = blockIdx.x * 256 + threadIdx.x;
    int lane = t & 31;
    int mb = (t >> 5) & 255;
    int k8 = t >> 13;
    int kq = lane & 3, gq = lane >> 2;
    int m = mb * 16 + gq;
    int k = k8 * 8 + kq;
    const float* src = (k < UDIM) ? (x + k) : (h + (k - UDIM));
    uint4 u;
    u.x = tf32r(src[(size_t)m * UDIM]);
    u.y = tf32r(src[(size_t)(m + 8) * UDIM]);
    u.z = tf32r(src[(size_t)m * UDIM + 4]);
    u.w = tf32r(src[(size_t)(m + 8) * UDIM + 4]);
    *(uint4*)(g_Ap + (size_t)t * 4) = u;
}

__global__ void __launch_bounds__(256) pack_W_kernel(
    const float* __restrict__ wxf, const float* __restrict__ wxi,
    const float* __restrict__ wxo, const float* __restrict__ wxg,
    const float* __restrict__ whf, const float* __restrict__ whi,
    const float* __restrict__ who, const float* __restrict__ whg)
{
    uint32_t t = blockIdx.x * 256 + threadIdx.x;
    int lane = t & 31;
    int nb = (t >> 5) & 1023;
    int k8 = t >> 15;
    int kq = lane & 3, nq = lane >> 2;
    int n = nb * 8 + nq;
    int u = n >> 2, g = n & 3;
    int k = k8 * 8 + kq;
    const float* W;
    if (k < UDIM) {
        W = (g == 0) ? wxf : (g == 1) ? wxi : (g == 2) ? wxo : wxg;
    } else {
        W = (g == 0) ? whf : (g == 1) ? whi : (g == 2) ? who : whg;
        k -= UDIM;
    }
    float2 v;
    v.x = __uint_as_float(tf32r(W[(size_t)k * UDIM + u]));
    v.y = __uint_as_float(tf32r(W[(size_t)(k + 4) * UDIM + u]));
    *(float2*)(g_Bp + (size_t)t * 2) = v;
}

// ---------------------------------------------------------------- GEMM
__device__ __forceinline__ void load_stage(uint32_t sbase, int slot, int kt,
                                           int tid, int mb0, int nb0)
{
    uint32_t sa = sbase + slot * STAGE_BYTES;
    uint32_t sb = sa + SA_STAGE;
    const int k8 = kt * 2;
    const float* a0 = g_Ap + (size_t)k8 * (MBTOT * 128) + mb0 * 128;
    const float* b0 = g_Bp + (size_t)k8 * (NBTOT * 64) + nb0 * 64;
    // A: 2 x 8KB linear (k8, k8+1)
    cp16(sa + tid * 16, a0 + tid * 4);
    cp16(sa + 8192 + tid * 16, a0 + MBTOT * 128 + tid * 4);
    // B: 2 x 8KB linear
    cp16(sb + tid * 16, b0 + tid * 4);
    cp16(sb + 8192 + tid * 16, b0 + NBTOT * 64 + tid * 4);
}

__global__ void __launch_bounds__(NTHREADS, 1) lstm_gemm_kernel(
    const float* __restrict__ cin,
    const float* __restrict__ bfp, const float* __restrict__ bip,
    const float* __restrict__ bop, const float* __restrict__ bgp,
    float* __restrict__ out)
{
    extern __shared__ char smem[];
    const uint32_t sbase = smem_u32(smem);
    const int tid = threadIdx.x;
    const int wid = tid >> 5;
    const int lane = tid & 31;
    const int mt = blockIdx.x & 15;          // m fastest: A stays L2-resident
    const int nt = blockIdx.x >> 4;          // 0..31
    const int mb0 = mt * 16;
    const int nb0 = nt * 32;

    const int wmi = wid & 3;                 // warp m index (64-row tile)
    const int wni = wid >> 2;                // warp n index (64-col tile)
    const uint32_t a_off = (uint32_t)wmi * 2048 + lane * 16;
    const uint32_t b_off = (uint32_t)wni * 2048 + lane * 8;

    float acc[4][8][4];
#pragma unroll
    for (int mf = 0; mf < 4; mf++)
#pragma unroll
        for (int nf = 0; nf < 8; nf++)
#pragma unroll
            for (int r = 0; r < 4; r++) acc[mf][nf][r] = 0.f;

#pragma unroll
    for (int s = 0; s < STAGES - 1; s++) {
        load_stage(sbase, s, s, tid, mb0, nb0);
        cp_commit();
    }

    const int KT = KTOT / TK;                // 256
    for (int kt = 0; kt < KT; kt++) {
        cp_wait<STAGES - 2>();
        __syncthreads();

        int nk = kt + STAGES - 1;
        if (nk < KT) load_stage(sbase, nk & (STAGES - 1), nk, tid, mb0, nb0);
        cp_commit();

        const uint32_t sa = sbase + (kt & (STAGES - 1)) * STAGE_BYTES;
        const uint32_t sb = sa + SA_STAGE;

#pragma unroll
        for (int ks = 0; ks < 2; ks++) {
            uint32_t a[4][4];
#pragma unroll
            for (int mf = 0; mf < 4; mf++) {
                uint32_t addr = sa + ks * 8192 + mf * 512 + a_off;
                asm volatile("ld.shared.v4.b32 {%0,%1,%2,%3}, [%4];"
                             : "=r"(a[mf][0]), "=r"(a[mf][1]),
                               "=r"(a[mf][2]), "=r"(a[mf][3])
                             : "r"(addr));
            }
            uint32_t b[8][2];
#pragma unroll
            for (int nf = 0; nf < 8; nf++) {
                uint32_t addr = sb + ks * 8192 + nf * 256 + b_off;
                asm volatile("ld.shared.v2.b32 {%0,%1}, [%2];"
                             : "=r"(b[nf][0]), "=r"(b[nf][1])
                             : "r"(addr));
            }
#pragma unroll
            for (int mf = 0; mf < 4; mf++)
#pragma unroll
                for (int nf = 0; nf < 8; nf++)
                    mma8(acc[mf][nf], a[mf], b[nf]);
        }
    }

    cp_wait<0>();

    // ---- epilogue: two 128-col halves through smem ----
    float* s_z = (float*)smem;
    const int gq = lane >> 2, kq = lane & 3;
    const int m0 = mt * TM;
    const size_t HC = (size_t)MTOT * UDIM;

#pragma unroll
    for (int hf = 0; hf < 2; hf++) {
        __syncthreads();   // previous half consumed / pipeline done
        if ((wni >> 1) == hf) {
#pragma unroll
            for (int mf = 0; mf < 4; mf++)
#pragma unroll
                for (int nf = 0; nf < 8; nf++) {
                    int row = wmi * 64 + mf * 16 + gq;
                    int col = (wni & 1) * 64 + nf * 8 + 2 * kq;
                    *(float2*)(s_z + row * ZLD + col) =
                        make_float2(acc[mf][nf][0], acc[mf][nf][1]);
                    *(float2*)(s_z + (row + 8) * ZLD + col) =
                        make_float2(acc[mf][nf][2], acc[mf][nf][3]);
                }
        }
        __syncthreads();

        const int ul = tid & 31;             // unit lane within 32-unit half
        const int rb = tid >> 5;             // 16 row blocks of 16 rows
        const int u = nt * 64 + hf * 32 + ul;
        const float bf = __ldg(bfp + u);
        const float bi = __ldg(bip + u);
        const float bo = __ldg(bop + u);
        const float bg = __ldg(bgp + u);

#pragma unroll 4
        for (int rr = 0; rr < 16; rr++) {
            int row = rb * 16 + rr;
            float4 z = *(const float4*)(s_z + row * ZLD + 4 * ul);
            size_t g = (size_t)(m0 + row) * UDIM + u;
            float zf = z.x + bf, zi = z.y + bi, zo = z.z + bo, zg = z.w + bg;
            float fg = 1.f / (1.f + expf(-zf));
            float ig = 1.f / (1.f + expf(-zi));
            float og = 1.f / (1.f + expf(-zo));
            float gg = tanhf(zg);
            float cn = fg * __ldg(cin + g) + ig * gg;
            float hn = og * tanhf(cn);
            out[g] = hn;          // h_new
            out[HC + g] = cn;     // c_new
        }
    }
}

// ---------------------------------------------------------------- launch
extern "C" void kernel_launch(void* const* d_in, const int* in_sizes, int n_in,
                              void* d_out, int out_size) {
    (void)in_sizes; (void)n_in; (void)out_size;
    const float* x   = (const float*)d_in[0];
    const float* h   = (const float*)d_in[1];
    const float* c   = (const float*)d_in[2];
    const float* Wxf = (const float*)d_in[3];
    const float* Wxi = (const float*)d_in[4];
    const float* Wxo = (const float*)d_in[5];
    const float* Wxg = (const float*)d_in[6];
    const float* bf  = (const float*)d_in[7];
    const float* bi  = (const float*)d_in[8];
    const float* bo  = (const float*)d_in[9];
    const float* bg  = (const float*)d_in[10];
    const float* Whf = (const float*)d_in[11];
    const float* Whi = (const float*)d_in[12];
    const float* Who = (const float*)d_in[13];
    const float* Whg = (const float*)d_in[14];
    float* out = (float*)d_out;

    static int smem_set = 0;
    if (!smem_set) {
        cudaFuncSetAttribute(lstm_gemm_kernel,
                             cudaFuncAttributeMaxDynamicSharedMemorySize,
                             SMEM_BYTES);
        smem_set = 1;
    }

    pack_A_kernel<<<(MTOT / 16) * (KTOT / 8) * 32 / 256, 256>>>(x, h);
    pack_W_kernel<<<(KTOT / 8) * (NTOT / 8) * 32 / 256, 256>>>(
        Wxf, Wxi, Wxo, Wxg, Whf, Whi, Who, Whg);
    lstm_gemm_kernel<<<(MTOT / TM) * (NTOT / TN), NTHREADS, SMEM_BYTES>>>(
        c, bf, bi, bo, bg, out);
}

// round 5
// speedup vs baseline: 2.4012x; 2.4012x over previous
#include <cuda_runtime.h>
#include <cstdint>

// ============================================================================
// LSTM cell, base sm_103 ISA. tf32 mma.sync m16n8k8, cp.async 4-stage,
// fragment-packed operands. CTA 256x128 with 256 threads, warp tile 64x64
// (128 acc regs/thread -- legal at 256 thr/CTA, spilled at 512 in R4).
// Fused gate epilogue in two 128-row halves.
//
// z[4096, 8192] = A[4096, 4096] @ B[4096, 8192]
//   A = [x | h], B[k][4u+g] = W{x,h}{f,i,o,g}[k][u]  (gate-interleaved)
// ============================================================================

#define MTOT 4096
#define KTOT 4096
#define NTOT 8192
#define UDIM 2048

#define TM 256
#define TN 128
#define TK 16          // 2 k8 sub-steps per stage
#define STAGES 4
#define NTHREADS 256

#define MBTOT 256              // MTOT/16
#define NBTOT 1024             // NTOT/8

#define SA_STAGE 16384         // 2 k8 * 16 mb * 512 B
#define SB_STAGE 8192          // 2 k8 * 16 nb * 256 B
#define STAGE_BYTES (SA_STAGE + SB_STAGE)      // 24576
#define PIPE_BYTES (STAGES * STAGE_BYTES)      // 98304
#define ZLD 132
#define Z_BYTES (128 * ZLD * 4)                // 67584 (one 128-row half)
#define SMEM_BYTES PIPE_BYTES

// Fragment-packed tf32 operands.
// g_Ap[k8][mb][lane][4] : lane=(gq<<2)|kq holds A[mb*16+gq+{0,8}][k8*8+kq+{0,4}]
// g_Bp[k8][nb][lane][2] : lane=(nq<<2)|kq holds B[k8*8+kq+{0,4}][nb*8+nq]
static __device__ __align__(16) float g_Ap[(size_t)MTOT * KTOT];   // 64 MB
static __device__ __align__(16) float g_Bp[(size_t)KTOT * NTOT];   // 128 MB

// ---------------------------------------------------------------- helpers
__device__ __forceinline__ uint32_t smem_u32(const void* p) {
    uint32_t a;
    asm("{ .reg .u64 t; cvta.to.shared.u64 t, %1; cvt.u32.u64 %0, t; }"
        : "=r"(a) : "l"(p));
    return a;
}

__device__ __forceinline__ uint32_t tf32r(float v) {   // round-to-nearest tf32
    uint32_t r;
    asm("cvt.rna.tf32.f32 %0, %1;" : "=r"(r) : "f"(v));
    return r;
}

__device__ __forceinline__ void cp16(uint32_t dst, const void* src) {
    asm volatile("cp.async.cg.shared.global [%0], [%1], 16;"
                 :: "r"(dst), "l"(src) : "memory");
}
__device__ __forceinline__ void cp_commit() {
    asm volatile("cp.async.commit_group;" ::: "memory");
}
template <int N>
__device__ __forceinline__ void cp_wait() {
    asm volatile("cp.async.wait_group %0;" :: "n"(N) : "memory");
}

__device__ __forceinline__ void mma8(float* d, const uint32_t* a, const uint32_t* b) {
    asm volatile(
        "mma.sync.aligned.m16n8k8.row.col.f32.tf32.tf32.f32 "
        "{%0,%1,%2,%3}, {%4,%5,%6,%7}, {%8,%9}, {%0,%1,%2,%3};"
        : "+f"(d[0]), "+f"(d[1]), "+f"(d[2]), "+f"(d[3])
        : "r"(a[0]), "r"(a[1]), "r"(a[2]), "r"(a[3]), "r"(b[0]), "r"(b[1]));
}

// ---------------------------------------------------------------- prepasses
__global__ void __launch_bounds__(256) pack_A_kernel(
    const float* __restrict__ x, const float* __restrict__ h)
{
    uint32_t t = blockIdx.x * 256 + threadIdx.x;
    int lane = t & 31;
    int mb = (t >> 5) & 255;
    int k8 = t >> 13;
    int kq = lane & 3, gq = lane >> 2;
    int m = mb * 16 + gq;
    int k = k8 * 8 + kq;
    const float* src = (k < UDIM) ? (x + k) : (h + (k - UDIM));
    uint4 u;
    u.x = tf32r(src[(size_t)m * UDIM]);
    u.y = tf32r(src[(size_t)(m + 8) * UDIM]);
    u.z = tf32r(src[(size_t)m * UDIM + 4]);
    u.w = tf32r(src[(size_t)(m + 8) * UDIM + 4]);
    *(uint4*)(g_Ap + (size_t)t * 4) = u;
}

__global__ void __launch_bounds__(256) pack_W_kernel(
    const float* __restrict__ wxf, const float* __restrict__ wxi,
    const float* __restrict__ wxo, const float* __restrict__ wxg,
    const float* __restrict__ whf, const float* __restrict__ whi,
    const float* __restrict__ who, const float* __restrict__ whg)
{
    uint32_t t = blockIdx.x * 256 + threadIdx.x;
    int lane = t & 31;
    int nb = (t >> 5) & 1023;
    int k8 = t >> 15;
    int kq = lane & 3, nq = lane >> 2;
    int n = nb * 8 + nq;
    int u = n >> 2, g = n & 3;
    int k = k8 * 8 + kq;
    const float* W;
    if (k < UDIM) {
        W = (g == 0) ? wxf : (g == 1) ? wxi : (g == 2) ? wxo : wxg;
    } else {
        W = (g == 0) ? whf : (g == 1) ? whi : (g == 2) ? who : whg;
        k -= UDIM;
    }
    float2 v;
    v.x = __uint_as_float(tf32r(W[(size_t)k * UDIM + u]));
    v.y = __uint_as_float(tf32r(W[(size_t)(k + 4) * UDIM + u]));
    *(float2*)(g_Bp + (size_t)t * 2) = v;
}

// ---------------------------------------------------------------- GEMM
__device__ __forceinline__ void load_stage(uint32_t sbase, int slot, int kt,
                                           int tid, int mb0, int nb0)
{
    uint32_t sa = sbase + slot * STAGE_BYTES;
    uint32_t sb = sa + SA_STAGE;
    const int k8 = kt * 2;
    const float* a0 = g_Ap + (size_t)k8 * (MBTOT * 128) + mb0 * 128;
    const float* b0 = g_Bp + (size_t)k8 * (NBTOT * 64) + nb0 * 64;
    // A: per k8, 8KB = 2 x 4KB rounds; two k8 slabs
    cp16(sa + tid * 16,         a0 + tid * 4);
    cp16(sa + 4096 + tid * 16,  a0 + 1024 + tid * 4);
    cp16(sa + 8192 + tid * 16,  a0 + MBTOT * 128 + tid * 4);
    cp16(sa + 12288 + tid * 16, a0 + MBTOT * 128 + 1024 + tid * 4);
    // B: per k8, 4KB = 1 round; two k8 slabs
    cp16(sb + tid * 16,         b0 + tid * 4);
    cp16(sb + 4096 + tid * 16,  b0 + NBTOT * 64 + tid * 4);
}

__global__ void __launch_bounds__(NTHREADS, 1) lstm_gemm_kernel(
    const float* __restrict__ cin,
    const float* __restrict__ bfp, const float* __restrict__ bip,
    const float* __restrict__ bop, const float* __restrict__ bgp,
    float* __restrict__ out)
{
    extern __shared__ char smem[];
    const uint32_t sbase = smem_u32(smem);
    const int tid = threadIdx.x;
    const int wid = tid >> 5;
    const int lane = tid & 31;
    const int mt = blockIdx.x & 15;          // m fastest: A stays L2-resident
    const int nt = blockIdx.x >> 4;          // 0..63
    const int mb0 = mt * 16;
    const int nb0 = nt * 16;

    const int wmi = wid & 3;                 // warp m index (64-row tile)
    const int wni = wid >> 2;                // warp n index (64-col tile)
    const uint32_t a_off = (uint32_t)wmi * 2048 + lane * 16;
    const uint32_t b_off = (uint32_t)wni * 2048 + lane * 8;

    float acc[4][8][4];
#pragma unroll
    for (int mf = 0; mf < 4; mf++)
#pragma unroll
        for (int nf = 0; nf < 8; nf++)
#pragma unroll
            for (int r = 0; r < 4; r++) acc[mf][nf][r] = 0.f;

#pragma unroll
    for (int s = 0; s < STAGES - 1; s++) {
        load_stage(sbase, s, s, tid, mb0, nb0);
        cp_commit();
    }

    const int KT = KTOT / TK;                // 256
    for (int kt = 0; kt < KT; kt++) {
        cp_wait<STAGES - 2>();
        __syncthreads();

        int nk = kt + STAGES - 1;
        if (nk < KT) load_stage(sbase, nk & (STAGES - 1), nk, tid, mb0, nb0);
        cp_commit();

        const uint32_t sa = sbase + (kt & (STAGES - 1)) * STAGE_BYTES;
        const uint32_t sb = sa + SA_STAGE;

#pragma unroll
        for (int ks = 0; ks < 2; ks++) {
            uint32_t a[4][4];
#pragma unroll
            for (int mf = 0; mf < 4; mf++) {
                uint32_t addr = sa + ks * 8192 + mf * 512 + a_off;
                asm volatile("ld.shared.v4.b32 {%0,%1,%2,%3}, [%4];"
                             : "=r"(a[mf][0]), "=r"(a[mf][1]),
                               "=r"(a[mf][2]), "=r"(a[mf][3])
                             : "r"(addr));
            }
            uint32_t b[8][2];
#pragma unroll
            for (int nf = 0; nf < 8; nf++) {
                uint32_t addr = sb + ks * 4096 + nf * 256 + b_off;
                asm volatile("ld.shared.v2.b32 {%0,%1}, [%2];"
                             : "=r"(b[nf][0]), "=r"(b[nf][1])
                             : "r"(addr));
            }
#pragma unroll
            for (int mf = 0; mf < 4; mf++)
#pragma unroll
                for (int nf = 0; nf < 8; nf++)
                    mma8(acc[mf][nf], a[mf], b[nf]);
        }
    }

    cp_wait<0>();

    // ---- epilogue: two 128-row halves through smem ----
    float* s_z = (float*)smem;
    const int gq = lane >> 2, kq = lane & 3;
    const int m0 = mt * TM;
    const size_t HC = (size_t)MTOT * UDIM;
    const int ul = tid & 31;                 // unit lane (32 units per CTA)
    const int rb = tid >> 5;                 // 8 row blocks of 16 rows
    const int u = nt * 32 + ul;
    const float bf = __ldg(bfp + u);
    const float bi = __ldg(bip + u);
    const float bo = __ldg(bop + u);
    const float bg = __ldg(bgp + u);

#pragma unroll
    for (int hf = 0; hf < 2; hf++) {
        __syncthreads();   // pipeline done / previous half consumed
        if ((wmi >> 1) == hf) {
#pragma unroll
            for (int mf = 0; mf < 4; mf++)
#pragma unroll
                for (int nf = 0; nf < 8; nf++) {
                    int row = (wmi & 1) * 64 + mf * 16 + gq;
                    int col = wni * 64 + nf * 8 + 2 * kq;
                    *(float2*)(s_z + row * ZLD + col) =
                        make_float2(acc[mf][nf][0], acc[mf][nf][1]);
                    *(float2*)(s_z + (row + 8) * ZLD + col) =
                        make_float2(acc[mf][nf][2], acc[mf][nf][3]);
                }
        }
        __syncthreads();

#pragma unroll 4
        for (int rr = 0; rr < 16; rr++) {
            int row = rb * 16 + rr;
            float4 z = *(const float4*)(s_z + row * ZLD + 4 * ul);
            size_t g = (size_t)(m0 + hf * 128 + row) * UDIM + u;
            float zf = z.x + bf, zi = z.y + bi, zo = z.z + bo, zg = z.w + bg;
            float fg = 1.f / (1.f + expf(-zf));
            float ig = 1.f / (1.f + expf(-zi));
            float og = 1.f / (1.f + expf(-zo));
            float gg = tanhf(zg);
            float cn = fg * __ldg(cin + g) + ig * gg;
            float hn = og * tanhf(cn);
            out[g] = hn;          // h_new
            out[HC + g] = cn;     // c_new
        }
    }
}

// ---------------------------------------------------------------- launch
extern "C" void kernel_launch(void* const* d_in, const int* in_sizes, int n_in,
                              void* d_out, int out_size) {
    (void)in_sizes; (void)n_in; (void)out_size;
    const float* x   = (const float*)d_in[0];
    const float* h   = (const float*)d_in[1];
    const float* c   = (const float*)d_in[2];
    const float* Wxf = (const float*)d_in[3];
    const float* Wxi = (const float*)d_in[4];
    const float* Wxo = (const float*)d_in[5];
    const float* Wxg = (const float*)d_in[6];
    const float* bf  = (const float*)d_in[7];
    const float* bi  = (const float*)d_in[8];
    const float* bo  = (const float*)d_in[9];
    const float* bg  = (const float*)d_in[10];
    const float* Whf = (const float*)d_in[11];
    const float* Whi = (const float*)d_in[12];
    const float* Who = (const float*)d_in[13];
    const float* Whg = (const float*)d_in[14];
    float* out = (float*)d_out;

    static int smem_set = 0;
    if (!smem_set) {
        cudaFuncSetAttribute(lstm_gemm_kernel,
                             cudaFuncAttributeMaxDynamicSharedMemorySize,
                             SMEM_BYTES);
        smem_set = 1;
    }

    pack_A_kernel<<<(MTOT / 16) * (KTOT / 8) * 32 / 256, 256>>>(x, h);
    pack_W_kernel<<<(KTOT / 8) * (NTOT / 8) * 32 / 256, 256>>>(
        Wxf, Wxi, Wxo, Wxg, Whf, Whi, Who, Whg);
    lstm_gemm_kernel<<<(MTOT / TM) * (NTOT / TN), NTHREADS, SMEM_BYTES>>>(
        c, bf, bi, bo, bg, out);
}

// round 6
// speedup vs baseline: 2.6216x; 1.0918x over previous
#include <cuda_runtime.h>
#include <cstdint>

// ============================================================================
// LSTM cell, base sm_103 ISA. tf32 mma.sync m16n8k8, cp.async 3-stage TK=32,
// fragment-packed operands, register double-buffered fragments.
// CTA 256x128, 256 threads, warp tile 64x64. Fused gate epilogue.
//
// z[4096, 8192] = A[4096, 4096] @ B[4096, 8192]
//   A = [x | h], B[k][4u+g] = W{x,h}{f,i,o,g}[k][u]  (gate-interleaved)
// ============================================================================

#define MTOT 4096
#define KTOT 4096
#define NTOT 8192
#define UDIM 2048

#define TM 256
#define TN 128
#define TK 32          // 4 k8 sub-steps per stage
#define STAGES 3
#define NTHREADS 256

#define MBTOT 256              // MTOT/16
#define NBPTOT 512             // NTOT/16 (n-fragment pairs)

#define SA_STAGE 32768         // 4 k8 * 16 mb * 512 B
#define SB_STAGE 16384         // 4 k8 * 8 nbp * 512 B
#define STAGE_BYTES (SA_STAGE + SB_STAGE)      // 49152
#define PIPE_BYTES (STAGES * STAGE_BYTES)      // 147456
#define ZLD 132
#define SMEM_BYTES PIPE_BYTES

// Fragment-packed tf32 operands.
// g_Ap[k8][mb][lane][4] : lane=(gq<<2)|kq holds A[mb*16+gq+{0,8}][k8*8+kq+{0,4}]
// g_Bp[k8][nbp][lane][4]: lane=(nq<<2)|kq holds B[k8*8+kq+{0,4}][nbp*16+nq+{0,8}]
static __device__ __align__(16) float g_Ap[(size_t)MTOT * KTOT];   // 64 MB
static __device__ __align__(16) float g_Bp[(size_t)KTOT * NTOT];   // 128 MB

// ---------------------------------------------------------------- helpers
__device__ __forceinline__ uint32_t smem_u32(const void* p) {
    uint32_t a;
    asm("{ .reg .u64 t; cvta.to.shared.u64 t, %1; cvt.u32.u64 %0, t; }"
        : "=r"(a) : "l"(p));
    return a;
}

__device__ __forceinline__ uint32_t tf32r(float v) {   // round-to-nearest tf32
    uint32_t r;
    asm("cvt.rna.tf32.f32 %0, %1;" : "=r"(r) : "f"(v));
    return r;
}

__device__ __forceinline__ void cp16(uint32_t dst, const void* src) {
    asm volatile("cp.async.cg.shared.global [%0], [%1], 16;"
                 :: "r"(dst), "l"(src) : "memory");
}
__device__ __forceinline__ void cp_commit() {
    asm volatile("cp.async.commit_group;" ::: "memory");
}
template <int N>
__device__ __forceinline__ void cp_wait() {
    asm volatile("cp.async.wait_group %0;" :: "n"(N) : "memory");
}

__device__ __forceinline__ void mma8(float* d, const uint32_t* a, const uint32_t* b) {
    asm volatile(
        "mma.sync.aligned.m16n8k8.row.col.f32.tf32.tf32.f32 "
        "{%0,%1,%2,%3}, {%4,%5,%6,%7}, {%8,%9}, {%0,%1,%2,%3};"
        : "+f"(d[0]), "+f"(d[1]), "+f"(d[2]), "+f"(d[3])
        : "r"(a[0]), "r"(a[1]), "r"(a[2]), "r"(a[3]), "r"(b[0]), "r"(b[1]));
}

// ---------------------------------------------------------------- prepasses
__global__ void __launch_bounds__(256) pack_A_kernel(
    const float* __restrict__ x, const float* __restrict__ h)
{
    uint32_t t = blockIdx.x * 256 + threadIdx.x;
    int lane = t & 31;
    int mb = (t >> 5) & 255;
    int k8 = t >> 13;
    int kq = lane & 3, gq = lane >> 2;
    int m = mb * 16 + gq;
    int k = k8 * 8 + kq;
    const float* src = (k < UDIM) ? (x + k) : (h + (k - UDIM));
    uint4 u;
    u.x = tf32r(src[(size_t)m * UDIM]);
    u.y = tf32r(src[(size_t)(m + 8) * UDIM]);
    u.z = tf32r(src[(size_t)m * UDIM + 4]);
    u.w = tf32r(src[(size_t)(m + 8) * UDIM + 4]);
    *(uint4*)(g_Ap + (size_t)t * 4) = u;
}

// B pack, paired n-fragments: thread t = (k8, nbp, lane) writes uint4.
__global__ void __launch_bounds__(256) pack_W_kernel(
    const float* __restrict__ wxf, const float* __restrict__ wxi,
    const float* __restrict__ wxo, const float* __restrict__ wxg,
    const float* __restrict__ whf, const float* __restrict__ whi,
    const float* __restrict__ who, const float* __restrict__ whg)
{
    uint32_t t = blockIdx.x * 256 + threadIdx.x;     // 8,388,608 threads
    int lane = t & 31;
    int nbp = (t >> 5) & 511;
    int k8 = t >> 14;
    int kq = lane & 3, nq = lane >> 2;
    int n0 = nbp * 16 + nq;              // first fragment column
    int u0 = n0 >> 2, g = n0 & 3;        // n0 and n0+8 share gate g
    int k = k8 * 8 + kq;
    const float* W;
    if (k < UDIM) {
        W = (g == 0) ? wxf : (g == 1) ? wxi : (g == 2) ? wxo : wxg;
    } else {
        W = (g == 0) ? whf : (g == 1) ? whi : (g == 2) ? who : whg;
        k -= UDIM;
    }
    uint4 v;
    v.x = tf32r(W[(size_t)k * UDIM + u0]);
    v.y = tf32r(W[(size_t)(k + 4) * UDIM + u0]);
    v.z = tf32r(W[(size_t)k * UDIM + u0 + 2]);        // n0+8 -> u0+2, same gate
    v.w = tf32r(W[(size_t)(k + 4) * UDIM + u0 + 2]);
    *(uint4*)(g_Bp + (size_t)t * 4) = v;
}

// ---------------------------------------------------------------- GEMM
__device__ __forceinline__ void load_stage(uint32_t sbase, int slot, int kt,
                                           int tid, int mb0, int nbp0)
{
    uint32_t sa = sbase + slot * STAGE_BYTES;
    uint32_t sb = sa + SA_STAGE;
    const int k8 = kt * 4;
    const float* a0 = g_Ap + (size_t)k8 * (MBTOT * 128) + mb0 * 128;
    const float* b0 = g_Bp + (size_t)k8 * (NBPTOT * 128) + nbp0 * 128;
#pragma unroll
    for (int j = 0; j < 4; j++) {
        cp16(sa + j * 8192 + tid * 16,        a0 + (size_t)j * (MBTOT * 128) + tid * 4);
        cp16(sa + j * 8192 + 4096 + tid * 16, a0 + (size_t)j * (MBTOT * 128) + 1024 + tid * 4);
        cp16(sb + j * 4096 + tid * 16,        b0 + (size_t)j * (NBPTOT * 128) + tid * 4);
    }
}

__global__ void __launch_bounds__(NTHREADS, 1) lstm_gemm_kernel(
    const float* __restrict__ cin,
    const float* __restrict__ bfp, const float* __restrict__ bip,
    const float* __restrict__ bop, const float* __restrict__ bgp,
    float* __restrict__ out)
{
    extern __shared__ char smem[];
    const uint32_t sbase = smem_u32(smem);
    const int tid = threadIdx.x;
    const int wid = tid >> 5;
    const int lane = tid & 31;
    const int mt = blockIdx.x & 15;          // m fastest: A stays L2-resident
    const int nt = blockIdx.x >> 4;          // 0..63
    const int mb0 = mt * 16;
    const int nbp0 = nt * 8;

    const int wmi = wid & 3;                 // warp m index (64-row tile)
    const int wni = wid >> 2;                // warp n index (64-col tile)
    const uint32_t a_off = (uint32_t)wmi * 2048 + lane * 16;
    const uint32_t b_off = (uint32_t)wni * 2048 + lane * 16;

    float acc[4][8][4];
#pragma unroll
    for (int mf = 0; mf < 4; mf++)
#pragma unroll
        for (int nf = 0; nf < 8; nf++)
#pragma unroll
            for (int r = 0; r < 4; r++) acc[mf][nf][r] = 0.f;

    load_stage(sbase, 0, 0, tid, mb0, nbp0);
    cp_commit();
    load_stage(sbase, 1, 1, tid, mb0, nbp0);
    cp_commit();

    uint32_t a[2][4][4];
    uint32_t b[2][8][2];

    const int KT = KTOT / TK;                // 128
    int slot = 0, nslot = 2;
    for (int kt = 0; kt < KT; kt++) {
        cp_wait<STAGES - 2>();
        __syncthreads();

        if (kt + 2 < KT) load_stage(sbase, nslot, kt + 2, tid, mb0, nbp0);
        cp_commit();

        const uint32_t sa = sbase + slot * STAGE_BYTES;
        const uint32_t sb = sa + SA_STAGE;

        // prime buffer 0 with ks=0 fragments
#pragma unroll
        for (int mf = 0; mf < 4; mf++)
            asm volatile("ld.shared.v4.b32 {%0,%1,%2,%3}, [%4];"
                         : "=r"(a[0][mf][0]), "=r"(a[0][mf][1]),
                           "=r"(a[0][mf][2]), "=r"(a[0][mf][3])
                         : "r"(sa + mf * 512 + a_off));
#pragma unroll
        for (int p = 0; p < 4; p++)
            asm volatile("ld.shared.v4.b32 {%0,%1,%2,%3}, [%4];"
                         : "=r"(b[0][2 * p][0]), "=r"(b[0][2 * p][1]),
                           "=r"(b[0][2 * p + 1][0]), "=r"(b[0][2 * p + 1][1])
                         : "r"(sb + p * 512 + b_off));

#pragma unroll
        for (int ks = 0; ks < 4; ks++) {
            const int cur = ks & 1, nxt = cur ^ 1;
            if (ks < 3) {      // prefetch ks+1 while cur MMAs issue
#pragma unroll
                for (int mf = 0; mf < 4; mf++)
                    asm volatile("ld.shared.v4.b32 {%0,%1,%2,%3}, [%4];"
                                 : "=r"(a[nxt][mf][0]), "=r"(a[nxt][mf][1]),
                                   "=r"(a[nxt][mf][2]), "=r"(a[nxt][mf][3])
                                 : "r"(sa + (ks + 1) * 8192 + mf * 512 + a_off));
#pragma unroll
                for (int p = 0; p < 4; p++)
                    asm volatile("ld.shared.v4.b32 {%0,%1,%2,%3}, [%4];"
                                 : "=r"(b[nxt][2 * p][0]), "=r"(b[nxt][2 * p][1]),
                                   "=r"(b[nxt][2 * p + 1][0]), "=r"(b[nxt][2 * p + 1][1])
                                 : "r"(sb + (ks + 1) * 4096 + p * 512 + b_off));
            }
#pragma unroll
            for (int mf = 0; mf < 4; mf++)
#pragma unroll
                for (int nf = 0; nf < 8; nf++)
                    mma8(acc[mf][nf], a[cur][mf], b[cur][nf]);
        }

        slot = (slot == STAGES - 1) ? 0 : slot + 1;
        nslot = (nslot == STAGES - 1) ? 0 : nslot + 1;
    }

    cp_wait<0>();

    // ---- epilogue: two 128-row halves through smem ----
    float* s_z = (float*)smem;
    const int gq = lane >> 2, kq = lane & 3;
    const int m0 = mt * TM;
    const size_t HC = (size_t)MTOT * UDIM;
    const int ul = tid & 31;                 // unit lane (32 units per CTA)
    const int rb = tid >> 5;                 // 8 row blocks of 16 rows
    const int u = nt * 32 + ul;
    const float bf = __ldg(bfp + u);
    const float bi = __ldg(bip + u);
    const float bo = __ldg(bop + u);
    const float bg = __ldg(bgp + u);

#pragma unroll
    for (int hf = 0; hf < 2; hf++) {
        __syncthreads();   // pipeline done / previous half consumed
        if ((wmi >> 1) == hf) {
#pragma unroll
            for (int mf = 0; mf < 4; mf++)
#pragma unroll
                for (int nf = 0; nf < 8; nf++) {
                    int row = (wmi & 1) * 64 + mf * 16 + gq;
                    int col = wni * 64 + nf * 8 + 2 * kq;
                    *(float2*)(s_z + row * ZLD + col) =
                        make_float2(acc[mf][nf][0], acc[mf][nf][1]);
                    *(float2*)(s_z + (row + 8) * ZLD + col) =
                        make_float2(acc[mf][nf][2], acc[mf][nf][3]);
                }
        }
        __syncthreads();

#pragma unroll 4
        for (int rr = 0; rr < 16; rr++) {
            int row = rb * 16 + rr;
            float4 z = *(const float4*)(s_z + row * ZLD + 4 * ul);
            size_t g = (size_t)(m0 + hf * 128 + row) * UDIM + u;
            float zf = z.x + bf, zi = z.y + bi, zo = z.z + bo, zg = z.w + bg;
            float fg = 1.f / (1.f + expf(-zf));
            float ig = 1.f / (1.f + expf(-zi));
            float og = 1.f / (1.f + expf(-zo));
            float gg = tanhf(zg);
            float cn = fg * __ldg(cin + g) + ig * gg;
            float hn = og * tanhf(cn);
            out[g] = hn;          // h_new
            out[HC + g] = cn;     // c_new
        }
    }
}

// ---------------------------------------------------------------- launch
extern "C" void kernel_launch(void* const* d_in, const int* in_sizes, int n_in,
                              void* d_out, int out_size) {
    (void)in_sizes; (void)n_in; (void)out_size;
    const float* x   = (const float*)d_in[0];
    const float* h   = (const float*)d_in[1];
    const float* c   = (const float*)d_in[2];
    const float* Wxf = (const float*)d_in[3];
    const float* Wxi = (const float*)d_in[4];
    const float* Wxo = (const float*)d_in[5];
    const float* Wxg = (const float*)d_in[6];
    const float* bf  = (const float*)d_in[7];
    const float* bi  = (const float*)d_in[8];
    const float* bo  = (const float*)d_in[9];
    const float* bg  = (const float*)d_in[10];
    const float* Whf = (const float*)d_in[11];
    const float* Whi = (const float*)d_in[12];
    const float* Who = (const float*)d_in[13];
    const float* Whg = (const float*)d_in[14];
    float* out = (float*)d_out;

    static int smem_set = 0;
    if (!smem_set) {
        cudaFuncSetAttribute(lstm_gemm_kernel,
                             cudaFuncAttributeMaxDynamicSharedMemorySize,
                             SMEM_BYTES);
        smem_set = 1;
    }

    pack_A_kernel<<<(MTOT / 16) * (KTOT / 8) * 32 / 256, 256>>>(x, h);
    pack_W_kernel<<<(KTOT / 8) * (NTOT / 16) * 32 / 256, 256>>>(
        Wxf, Wxi, Wxo, Wxg, Whf, Whi, Who, Whg);
    lstm_gemm_kernel<<<(MTOT / TM) * (NTOT / TN), NTHREADS, SMEM_BYTES>>>(
        c, bf, bi, bo, bg, out);
}

// round 7
// speedup vs baseline: 2.6678x; 1.0176x over previous
#include <cuda_runtime.h>
#include <cstdint>

// ============================================================================
// LSTM cell, base sm_103 ISA. tf32 mma.sync m16n8k8, cp.async 3-stage TK=32,
// fragment-packed operands, register double-buffered fragments.
// CTA 256x128, 256 threads, warp tile 64x64. Fused gate epilogue.
// R7: pack_W rewritten as coalesced smem-tiled transpose (was ~12.5% sector
// efficiency on its gather loads).
//
// z[4096, 8192] = A[4096, 4096] @ B[4096, 8192]
//   A = [x | h], B[k][4u+g] = W{x,h}{f,i,o,g}[k][u]  (gate-interleaved)
// ============================================================================

#define MTOT 4096
#define KTOT 4096
#define NTOT 8192
#define UDIM 2048

#define TM 256
#define TN 128
#define TK 32          // 4 k8 sub-steps per stage
#define STAGES 3
#define NTHREADS 256

#define MBTOT 256              // MTOT/16
#define NBPTOT 512             // NTOT/16 (n-fragment pairs)

#define SA_STAGE 32768         // 4 k8 * 16 mb * 512 B
#define SB_STAGE 16384         // 4 k8 * 8 nbp * 512 B
#define STAGE_BYTES (SA_STAGE + SB_STAGE)      // 49152
#define PIPE_BYTES (STAGES * STAGE_BYTES)      // 147456
#define ZLD 132
#define SMEM_BYTES PIPE_BYTES

// Fragment-packed tf32 operands.
// g_Ap[k8][mb][lane][4] : lane=(gq<<2)|kq holds A[mb*16+gq+{0,8}][k8*8+kq+{0,4}]
// g_Bp[k8][nbp][lane][4]: lane=(nq<<2)|kq holds B[k8*8+kq+{0,4}][nbp*16+nq+{0,8}]
static __device__ __align__(16) float g_Ap[(size_t)MTOT * KTOT];   // 64 MB
static __device__ __align__(16) float g_Bp[(size_t)KTOT * NTOT];   // 128 MB

// ---------------------------------------------------------------- helpers
__device__ __forceinline__ uint32_t smem_u32(const void* p) {
    uint32_t a;
    asm("{ .reg .u64 t; cvta.to.shared.u64 t, %1; cvt.u32.u64 %0, t; }"
        : "=r"(a) : "l"(p));
    return a;
}

__device__ __forceinline__ uint32_t tf32r(float v) {   // round-to-nearest tf32
    uint32_t r;
    asm("cvt.rna.tf32.f32 %0, %1;" : "=r"(r) : "f"(v));
    return r;
}

__device__ __forceinline__ void cp16(uint32_t dst, const void* src) {
    asm volatile("cp.async.cg.shared.global [%0], [%1], 16;"
                 :: "r"(dst), "l"(src) : "memory");
}
__device__ __forceinline__ void cp_commit() {
    asm volatile("cp.async.commit_group;" ::: "memory");
}
template <int N>
__device__ __forceinline__ void cp_wait() {
    asm volatile("cp.async.wait_group %0;" :: "n"(N) : "memory");
}

__device__ __forceinline__ void mma8(float* d, const uint32_t* a, const uint32_t* b) {
    asm volatile(
        "mma.sync.aligned.m16n8k8.row.col.f32.tf32.tf32.f32 "
        "{%0,%1,%2,%3}, {%4,%5,%6,%7}, {%8,%9}, {%0,%1,%2,%3};"
        : "+f"(d[0]), "+f"(d[1]), "+f"(d[2]), "+f"(d[3])
        : "r"(a[0]), "r"(a[1]), "r"(a[2]), "r"(a[3]), "r"(b[0]), "r"(b[1]));
}

// ---------------------------------------------------------------- prepasses
__global__ void __launch_bounds__(256) pack_A_kernel(
    const float* __restrict__ x, const float* __restrict__ h)
{
    uint32_t t = blockIdx.x * 256 + threadIdx.x;
    int lane = t & 31;
    int mb = (t >> 5) & 255;
    int k8 = t >> 13;
    int kq = lane & 3, gq = lane >> 2;
    int m = mb * 16 + gq;
    int k = k8 * 8 + kq;
    const float* src = (k < UDIM) ? (x + k) : (h + (k - UDIM));
    uint4 u;
    u.x = tf32r(src[(size_t)m * UDIM]);
    u.y = tf32r(src[(size_t)(m + 8) * UDIM]);
    u.z = tf32r(src[(size_t)m * UDIM + 4]);
    u.w = tf32r(src[(size_t)(m + 8) * UDIM + 4]);
    *(uint4*)(g_Ap + (size_t)t * 4) = u;
}

// pack_W v2: coalesced tiled transpose.
// CTA covers 16 consecutive k-rows x 64 units x all 4 gates.
//  load : 4 matrices x 16 rows x 64 floats, coalesced, tf32-rounded -> smem
//  emit : fragment-packed uint4s, coalesced 16B/lane writes.
#define WLD 65   // smem row stride (64 + 1 pad); row = k_local*4 + gate
__global__ void __launch_bounds__(256) pack_W_kernel(
    const float* __restrict__ wxf, const float* __restrict__ wxi,
    const float* __restrict__ wxo, const float* __restrict__ wxg,
    const float* __restrict__ whf, const float* __restrict__ whi,
    const float* __restrict__ who, const float* __restrict__ whg)
{
    __shared__ uint32_t s_w[64 * WLD];
    const int tid = threadIdx.x;
    const int kb = blockIdx.x & 255;         // 256 k-blocks of 16
    const int ub = blockIdx.x >> 8;          // 32 unit-blocks of 64
    const int kbase = kb * 16;
    const int ubase = ub * 64;

    const bool isx = (kbase < UDIM);
    const int klocal = isx ? kbase : (kbase - UDIM);
    const float* Wg[4];
    Wg[0] = isx ? wxf : whf;
    Wg[1] = isx ? wxi : whi;
    Wg[2] = isx ? wxo : who;
    Wg[3] = isx ? wxg : whg;

    // load: per gate, 16 rows x 16 float4; thread -> (r = tid>>4, q = tid&15)
    const int r = tid >> 4, q = tid & 15;
#pragma unroll
    for (int g = 0; g < 4; g++) {
        float4 v = *(const float4*)(Wg[g] + (size_t)(klocal + r) * UDIM +
                                    ubase + q * 4);
        uint32_t* d = s_w + (r * 4 + g) * WLD + q * 4;
        d[0] = tf32r(v.x); d[1] = tf32r(v.y);
        d[2] = tf32r(v.z); d[3] = tf32r(v.w);
    }
    __syncthreads();

    // emit: 1024 uint4 outputs, 4 per thread, lane-coalesced
#pragma unroll
    for (int i = 0; i < 4; i++) {
        int o = tid + 256 * i;
        int lane = o & 31;
        int nbpl = (o >> 5) & 15;
        int k8l = o >> 9;                    // 0 or 1
        int kq = lane & 3, nq = lane >> 2;
        int g = nq & 3, b = nq >> 2;
        int ul = 4 * nbpl + b;
        int row0 = (k8l * 8 + kq) * 4 + g;
        int row1 = row0 + 16;                // +4 k-rows
        uint4 v;
        v.x = s_w[row0 * WLD + ul];
        v.y = s_w[row1 * WLD + ul];
        v.z = s_w[row0 * WLD + ul + 2];
        v.w = s_w[row1 * WLD + ul + 2];
        int k8 = kb * 2 + k8l;
        int nbp = ub * 16 + nbpl;
        *(uint4*)(g_Bp + ((size_t)k8 * NBPTOT + nbp) * 128 + lane * 4) = v;
    }
}

// ---------------------------------------------------------------- GEMM
__device__ __forceinline__ void load_stage(uint32_t sbase, int slot, int kt,
                                           int tid, int mb0, int nbp0)
{
    uint32_t sa = sbase + slot * STAGE_BYTES;
    uint32_t sb = sa + SA_STAGE;
    const int k8 = kt * 4;
    const float* a0 = g_Ap + (size_t)k8 * (MBTOT * 128) + mb0 * 128;
    const float* b0 = g_Bp + (size_t)k8 * (NBPTOT * 128) + nbp0 * 128;
#pragma unroll
    for (int j = 0; j < 4; j++) {
        cp16(sa + j * 8192 + tid * 16,        a0 + (size_t)j * (MBTOT * 128) + tid * 4);
        cp16(sa + j * 8192 + 4096 + tid * 16, a0 + (size_t)j * (MBTOT * 128) + 1024 + tid * 4);
        cp16(sb + j * 4096 + tid * 16,        b0 + (size_t)j * (NBPTOT * 128) + tid * 4);
    }
}

__global__ void __launch_bounds__(NTHREADS, 1) lstm_gemm_kernel(
    const float* __restrict__ cin,
    const float* __restrict__ bfp, const float* __restrict__ bip,
    const float* __restrict__ bop, const float* __restrict__ bgp,
    float* __restrict__ out)
{
    extern __shared__ char smem[];
    const uint32_t sbase = smem_u32(smem);
    const int tid = threadIdx.x;
    const int wid = tid >> 5;
    const int lane = tid & 31;
    const int mt = blockIdx.x & 15;          // m fastest: A stays L2-resident
    const int nt = blockIdx.x >> 4;          // 0..63
    const int mb0 = mt * 16;
    const int nbp0 = nt * 8;

    const int wmi = wid & 3;                 // warp m index (64-row tile)
    const int wni = wid >> 2;                // warp n index (64-col tile)
    const uint32_t a_off = (uint32_t)wmi * 2048 + lane * 16;
    const uint32_t b_off = (uint32_t)wni * 2048 + lane * 16;

    float acc[4][8][4];
#pragma unroll
    for (int mf = 0; mf < 4; mf++)
#pragma unroll
        for (int nf = 0; nf < 8; nf++)
#pragma unroll
            for (int r = 0; r < 4; r++) acc[mf][nf][r] = 0.f;

    load_stage(sbase, 0, 0, tid, mb0, nbp0);
    cp_commit();
    load_stage(sbase, 1, 1, tid, mb0, nbp0);
    cp_commit();

    uint32_t a[2][4][4];
    uint32_t b[2][8][2];

    const int KT = KTOT / TK;                // 128
    int slot = 0, nslot = 2;
    for (int kt = 0; kt < KT; kt++) {
        cp_wait<STAGES - 2>();
        __syncthreads();

        if (kt + 2 < KT) load_stage(sbase, nslot, kt + 2, tid, mb0, nbp0);
        cp_commit();

        const uint32_t sa = sbase + slot * STAGE_BYTES;
        const uint32_t sb = sa + SA_STAGE;

        // prime buffer 0 with ks=0 fragments
#pragma unroll
        for (int mf = 0; mf < 4; mf++)
            asm volatile("ld.shared.v4.b32 {%0,%1,%2,%3}, [%4];"
                         : "=r"(a[0][mf][0]), "=r"(a[0][mf][1]),
                           "=r"(a[0][mf][2]), "=r"(a[0][mf][3])
                         : "r"(sa + mf * 512 + a_off));
#pragma unroll
        for (int p = 0; p < 4; p++)
            asm volatile("ld.shared.v4.b32 {%0,%1,%2,%3}, [%4];"
                         : "=r"(b[0][2 * p][0]), "=r"(b[0][2 * p][1]),
                           "=r"(b[0][2 * p + 1][0]), "=r"(b[0][2 * p + 1][1])
                         : "r"(sb + p * 512 + b_off));

#pragma unroll
        for (int ks = 0; ks < 4; ks++) {
            const int cur = ks & 1, nxt = cur ^ 1;
            if (ks < 3) {      // prefetch ks+1 while cur MMAs issue
#pragma unroll
                for (int mf = 0; mf < 4; mf++)
                    asm volatile("ld.shared.v4.b32 {%0,%1,%2,%3}, [%4];"
                                 : "=r"(a[nxt][mf][0]), "=r"(a[nxt][mf][1]),
                                   "=r"(a[nxt][mf][2]), "=r"(a[nxt][mf][3])
                                 : "r"(sa + (ks + 1) * 8192 + mf * 512 + a_off));
#pragma unroll
                for (int p = 0; p < 4; p++)
                    asm volatile("ld.shared.v4.b32 {%0,%1,%2,%3}, [%4];"
                                 : "=r"(b[nxt][2 * p][0]), "=r"(b[nxt][2 * p][1]),
                                   "=r"(b[nxt][2 * p + 1][0]), "=r"(b[nxt][2 * p + 1][1])
                                 : "r"(sb + (ks + 1) * 4096 + p * 512 + b_off));
            }
#pragma unroll
            for (int mf = 0; mf < 4; mf++)
#pragma unroll
                for (int nf = 0; nf < 8; nf++)
                    mma8(acc[mf][nf], a[cur][mf], b[cur][nf]);
        }

        slot = (slot == STAGES - 1) ? 0 : slot + 1;
        nslot = (nslot == STAGES - 1) ? 0 : nslot + 1;
    }

    cp_wait<0>();

    // ---- epilogue: two 128-row halves through smem ----
    float* s_z = (float*)smem;
    const int gq = lane >> 2, kq = lane & 3;
    const int m0 = mt * TM;
    const size_t HC = (size_t)MTOT * UDIM;
    const int ul = tid & 31;                 // unit lane (32 units per CTA)
    const int rb = tid >> 5;                 // 8 row blocks of 16 rows
    const int u = nt * 32 + ul;
    const float bf = __ldg(bfp + u);
    const float bi = __ldg(bip + u);
    const float bo = __ldg(bop + u);
    const float bg = __ldg(bgp + u);

#pragma unroll
    for (int hf = 0; hf < 2; hf++) {
        __syncthreads();   // pipeline done / previous half consumed
        if ((wmi >> 1) == hf) {
#pragma unroll
            for (int mf = 0; mf < 4; mf++)
#pragma unroll
                for (int nf = 0; nf < 8; nf++) {
                    int row = (wmi & 1) * 64 + mf * 16 + gq;
                    int col = wni * 64 + nf * 8 + 2 * kq;
                    *(float2*)(s_z + row * ZLD + col) =
                        make_float2(acc[mf][nf][0], acc[mf][nf][1]);
                    *(float2*)(s_z + (row + 8) * ZLD + col) =
                        make_float2(acc[mf][nf][2], acc[mf][nf][3]);
                }
        }
        __syncthreads();

#pragma unroll 4
        for (int rr = 0; rr < 16; rr++) {
            int row = rb * 16 + rr;
            float4 z = *(const float4*)(s_z + row * ZLD + 4 * ul);
            size_t g = (size_t)(m0 + hf * 128 + row) * UDIM + u;
            float zf = z.x + bf, zi = z.y + bi, zo = z.z + bo, zg = z.w + bg;
            float fg = 1.f / (1.f + expf(-zf));
            float ig = 1.f / (1.f + expf(-zi));
            float og = 1.f / (1.f + expf(-zo));
            float gg = tanhf(zg);
            float cn = fg * __ldg(cin + g) + ig * gg;
            float hn = og * tanhf(cn);
            out[g] = hn;          // h_new
            out[HC + g] = cn;     // c_new
        }
    }
}

// ---------------------------------------------------------------- launch
extern "C" void kernel_launch(void* const* d_in, const int* in_sizes, int n_in,
                              void* d_out, int out_size) {
    (void)in_sizes; (void)n_in; (void)out_size;
    const float* x   = (const float*)d_in[0];
    const float* h   = (const float*)d_in[1];
    const float* c   = (const float*)d_in[2];
    const float* Wxf = (const float*)d_in[3];
    const float* Wxi = (const float*)d_in[4];
    const float* Wxo = (const float*)d_in[5];
    const float* Wxg = (const float*)d_in[6];
    const float* bf  = (const float*)d_in[7];
    const float* bi  = (const float*)d_in[8];
    const float* bo  = (const float*)d_in[9];
    const float* bg  = (const float*)d_in[10];
    const float* Whf = (const float*)d_in[11];
    const float* Whi = (const float*)d_in[12];
    const float* Who = (const float*)d_in[13];
    const float* Whg = (const float*)d_in[14];
    float* out = (float*)d_out;

    static int smem_set = 0;
    if (!smem_set) {
        cudaFuncSetAttribute(lstm_gemm_kernel,
                             cudaFuncAttributeMaxDynamicSharedMemorySize,
                             SMEM_BYTES);
        smem_set = 1;
    }

    pack_A_kernel<<<(MTOT / 16) * (KTOT / 8) * 32 / 256, 256>>>(x, h);
    pack_W_kernel<<<(KTOT / 16) * (NTOT / 256), 256>>>(
        Wxf, Wxi, Wxo, Wxg, Whf, Whi, Who, Whg);
    lstm_gemm_kernel<<<(MTOT / TM) * (NTOT / TN), NTHREADS, SMEM_BYTES>>>(
        c, bf, bi, bo, bg, out);
}

// round 8
// speedup vs baseline: 3.0798x; 1.1544x over previous
#include <cuda_runtime.h>
#include <cstdint>

// ============================================================================
// LSTM cell, base sm_103 ISA. tf32 mma.sync m16n8k8, cp.async 4-stage TK=32,
// fragment-packed operands, register double-buffered fragments with
// CROSS-STAGE prefetch (no per-kt prime bubble). CTA 256x128, 256 threads,
// warp tile 64x64. Fused gate epilogue. Packs fused into one launch.
//
// z[4096, 8192] = A[4096, 4096] @ B[4096, 8192]
//   A = [x | h], B[k][4u+g] = W{x,h}{f,i,o,g}[k][u]  (gate-interleaved)
// ============================================================================

#define MTOT 4096
#define KTOT 4096
#define NTOT 8192
#define UDIM 2048

#define TM 256
#define TN 128
#define TK 32          // 4 k8 sub-steps per stage
#define STAGES 4
#define NTHREADS 256

#define MBTOT 256              // MTOT/16
#define NBPTOT 512             // NTOT/16 (n-fragment pairs)

#define SA_STAGE 32768         // 4 k8 * 16 mb * 512 B
#define SB_STAGE 16384         // 4 k8 * 8 nbp * 512 B
#define STAGE_BYTES (SA_STAGE + SB_STAGE)      // 49152
#define PIPE_BYTES (STAGES * STAGE_BYTES)      // 196608
#define ZLD 132
#define SMEM_BYTES PIPE_BYTES

// Fragment-packed tf32 operands.
// g_Ap[k8][mb][lane][4] : lane=(gq<<2)|kq holds A[mb*16+gq+{0,8}][k8*8+kq+{0,4}]
// g_Bp[k8][nbp][lane][4]: lane=(nq<<2)|kq holds B[k8*8+kq+{0,4}][nbp*16+nq+{0,8}]
static __device__ __align__(16) float g_Ap[(size_t)MTOT * KTOT];   // 64 MB
static __device__ __align__(16) float g_Bp[(size_t)KTOT * NTOT];   // 128 MB

// ---------------------------------------------------------------- helpers
__device__ __forceinline__ uint32_t smem_u32(const void* p) {
    uint32_t a;
    asm("{ .reg .u64 t; cvta.to.shared.u64 t, %1; cvt.u32.u64 %0, t; }"
        : "=r"(a) : "l"(p));
    return a;
}

__device__ __forceinline__ uint32_t tf32r(float v) {   // round-to-nearest tf32
    uint32_t r;
    asm("cvt.rna.tf32.f32 %0, %1;" : "=r"(r) : "f"(v));
    return r;
}

__device__ __forceinline__ void cp16(uint32_t dst, const void* src) {
    asm volatile("cp.async.cg.shared.global [%0], [%1], 16;"
                 :: "r"(dst), "l"(src) : "memory");
}
__device__ __forceinline__ void cp_commit() {
    asm volatile("cp.async.commit_group;" ::: "memory");
}
template <int N>
__device__ __forceinline__ void cp_wait() {
    asm volatile("cp.async.wait_group %0;" :: "n"(N) : "memory");
}

__device__ __forceinline__ void mma8(float* d, const uint32_t* a, const uint32_t* b) {
    asm volatile(
        "mma.sync.aligned.m16n8k8.row.col.f32.tf32.tf32.f32 "
        "{%0,%1,%2,%3}, {%4,%5,%6,%7}, {%8,%9}, {%0,%1,%2,%3};"
        : "+f"(d[0]), "+f"(d[1]), "+f"(d[2]), "+f"(d[3])
        : "r"(a[0]), "r"(a[1]), "r"(a[2]), "r"(a[3]), "r"(b[0]), "r"(b[1]));
}

__device__ __forceinline__ void lds128(uint32_t* r, uint32_t addr) {
    asm volatile("ld.shared.v4.b32 {%0,%1,%2,%3}, [%4];"
                 : "=r"(r[0]), "=r"(r[1]), "=r"(r[2]), "=r"(r[3]) : "r"(addr));
}

// ---------------------------------------------------------------- prepasses
#define NA_BLOCKS 16384        // pack_A part
#define NW_BLOCKS 8192         // pack_W part
#define WLD 65                 // pack_W smem row stride

__device__ void pack_A_body(const float* __restrict__ x,
                            const float* __restrict__ h, int blk)
{
    uint32_t t = blk * 256 + threadIdx.x;
    int lane = t & 31;
    int mb = (t >> 5) & 255;
    int k8 = t >> 13;
    int kq = lane & 3, gq = lane >> 2;
    int m = mb * 16 + gq;
    int k = k8 * 8 + kq;
    const float* src = (k < UDIM) ? (x + k) : (h + (k - UDIM));
    uint4 u;
    u.x = tf32r(src[(size_t)m * UDIM]);
    u.y = tf32r(src[(size_t)(m + 8) * UDIM]);
    u.z = tf32r(src[(size_t)m * UDIM + 4]);
    u.w = tf32r(src[(size_t)(m + 8) * UDIM + 4]);
    *(uint4*)(g_Ap + (size_t)t * 4) = u;
}

__device__ void pack_W_body(
    uint32_t* s_w,
    const float* __restrict__ wxf, const float* __restrict__ wxi,
    const float* __restrict__ wxo, const float* __restrict__ wxg,
    const float* __restrict__ whf, const float* __restrict__ whi,
    const float* __restrict__ who, const float* __restrict__ whg, int blk)
{
    const int tid = threadIdx.x;
    const int kb = blk & 255;                // 256 k-blocks of 16
    const int ub = blk >> 8;                 // 32 unit-blocks of 64
    const int kbase = kb * 16;
    const int ubase = ub * 64;

    const bool isx = (kbase < UDIM);
    const int klocal = isx ? kbase : (kbase - UDIM);
    const float* Wg[4];
    Wg[0] = isx ? wxf : whf;
    Wg[1] = isx ? wxi : whi;
    Wg[2] = isx ? wxo : who;
    Wg[3] = isx ? wxg : whg;

    const int r = tid >> 4, q = tid & 15;
#pragma unroll
    for (int g = 0; g < 4; g++) {
        float4 v = *(const float4*)(Wg[g] + (size_t)(klocal + r) * UDIM +
                                    ubase + q * 4);
        uint32_t* d = s_w + (r * 4 + g) * WLD + q * 4;
        d[0] = tf32r(v.x); d[1] = tf32r(v.y);
        d[2] = tf32r(v.z); d[3] = tf32r(v.w);
    }
    __syncthreads();

#pragma unroll
    for (int i = 0; i < 4; i++) {
        int o = tid + 256 * i;
        int lane = o & 31;
        int nbpl = (o >> 5) & 15;
        int k8l = o >> 9;
        int kq = lane & 3, nq = lane >> 2;
        int g = nq & 3, b = nq >> 2;
        int ul = 4 * nbpl + b;
        int row0 = (k8l * 8 + kq) * 4 + g;
        int row1 = row0 + 16;
        uint4 v;
        v.x = s_w[row0 * WLD + ul];
        v.y = s_w[row1 * WLD + ul];
        v.z = s_w[row0 * WLD + ul + 2];
        v.w = s_w[row1 * WLD + ul + 2];
        int k8 = kb * 2 + k8l;
        int nbp = ub * 16 + nbpl;
        *(uint4*)(g_Bp + ((size_t)k8 * NBPTOT + nbp) * 128 + lane * 4) = v;
    }
}

__global__ void __launch_bounds__(256) pack_AW_kernel(
    const float* __restrict__ x, const float* __restrict__ h,
    const float* __restrict__ wxf, const float* __restrict__ wxi,
    const float* __restrict__ wxo, const float* __restrict__ wxg,
    const float* __restrict__ whf, const float* __restrict__ whi,
    const float* __restrict__ who, const float* __restrict__ whg)
{
    __shared__ uint32_t s_w[64 * WLD];
    if (blockIdx.x < NA_BLOCKS)
        pack_A_body(x, h, blockIdx.x);
    else
        pack_W_body(s_w, wxf, wxi, wxo, wxg, whf, whi, who, whg,
                    blockIdx.x - NA_BLOCKS);
}

// ---------------------------------------------------------------- GEMM
__device__ __forceinline__ void load_stage(uint32_t sbase, int slot, int kt,
                                           int tid, int mb0, int nbp0)
{
    uint32_t sa = sbase + slot * STAGE_BYTES;
    uint32_t sb = sa + SA_STAGE;
    const int k8 = kt * 4;
    const float* a0 = g_Ap + (size_t)k8 * (MBTOT * 128) + mb0 * 128;
    const float* b0 = g_Bp + (size_t)k8 * (NBPTOT * 128) + nbp0 * 128;
#pragma unroll
    for (int j = 0; j < 4; j++) {
        cp16(sa + j * 8192 + tid * 16,        a0 + (size_t)j * (MBTOT * 128) + tid * 4);
        cp16(sa + j * 8192 + 4096 + tid * 16, a0 + (size_t)j * (MBTOT * 128) + 1024 + tid * 4);
        cp16(sb + j * 4096 + tid * 16,        b0 + (size_t)j * (NBPTOT * 128) + tid * 4);
    }
}

__global__ void __launch_bounds__(NTHREADS, 1) lstm_gemm_kernel(
    const float* __restrict__ cin,
    const float* __restrict__ bfp, const float* __restrict__ bip,
    const float* __restrict__ bop, const float* __restrict__ bgp,
    float* __restrict__ out)
{
    extern __shared__ char smem[];
    const uint32_t sbase = smem_u32(smem);
    const int tid = threadIdx.x;
    const int wid = tid >> 5;
    const int lane = tid & 31;
    const int mt = blockIdx.x & 15;          // m fastest: A stays L2-resident
    const int nt = blockIdx.x >> 4;          // 0..63
    const int mb0 = mt * 16;
    const int nbp0 = nt * 8;

    const int wmi = wid & 3;                 // warp m index (64-row tile)
    const int wni = wid >> 2;                // warp n index (64-col tile)
    const uint32_t a_off = (uint32_t)wmi * 2048 + lane * 16;
    const uint32_t b_off = (uint32_t)wni * 2048 + lane * 16;

    float acc[4][8][4];
#pragma unroll
    for (int mf = 0; mf < 4; mf++)
#pragma unroll
        for (int nf = 0; nf < 8; nf++)
#pragma unroll
            for (int r = 0; r < 4; r++) acc[mf][nf][r] = 0.f;

    // prologue: 3 stages in flight
#pragma unroll
    for (int s = 0; s < 3; s++) {
        load_stage(sbase, s, s, tid, mb0, nbp0);
        cp_commit();
    }
    cp_wait<2>();            // stage 0 complete (self)
    __syncthreads();         // visible to all

    uint32_t a[2][4][4];
    uint32_t b[2][8][2];

    // prime buffer 0 with (kt=0, ks=0) fragments
#pragma unroll
    for (int mf = 0; mf < 4; mf++)
        lds128(a[0][mf], sbase + mf * 512 + a_off);
#pragma unroll
    for (int p = 0; p < 4; p++)
        lds128(&b[0][2 * p][0], sbase + SA_STAGE + p * 512 + b_off);

    const int KT = KTOT / TK;                // 128
    for (int kt = 0; kt < KT; kt++) {
        const uint32_t sa = sbase + (kt & 3) * STAGE_BYTES;
        const uint32_t sb = sa + SA_STAGE;
        const uint32_t sa_n = sbase + ((kt + 1) & 3) * STAGE_BYTES;
        const uint32_t sb_n = sa_n + SA_STAGE;

        __syncthreads();                     // (A) readers of old slot done
        if (kt + 3 < KT) load_stage(sbase, (kt + 3) & 3, kt + 3, tid, mb0, nbp0);
        cp_commit();
        cp_wait<2>();                        // stage kt+1 complete (self)
        __syncthreads();                     // (B) stage kt+1 visible to all

#pragma unroll
        for (int ks = 0; ks < 4; ks++) {
            const int cur = ks & 1, nxt = cur ^ 1;
            if (ks < 3) {        // prefetch next ks of this stage
#pragma unroll
                for (int mf = 0; mf < 4; mf++)
                    lds128(a[nxt][mf], sa + (ks + 1) * 8192 + mf * 512 + a_off);
#pragma unroll
                for (int p = 0; p < 4; p++)
                    lds128(&b[nxt][2 * p][0], sb + (ks + 1) * 4096 + p * 512 + b_off);
            } else if (kt + 1 < KT) {   // prefetch ks=0 of NEXT stage
#pragma unroll
                for (int mf = 0; mf < 4; mf++)
                    lds128(a[nxt][mf], sa_n + mf * 512 + a_off);
#pragma unroll
                for (int p = 0; p < 4; p++)
                    lds128(&b[nxt][2 * p][0], sb_n + p * 512 + b_off);
            }
#pragma unroll
            for (int mf = 0; mf < 4; mf++)
#pragma unroll
                for (int nf = 0; nf < 8; nf++)
                    mma8(acc[mf][nf], a[cur][mf], b[cur][nf]);
        }
    }

    cp_wait<0>();

    // ---- epilogue: two 128-row halves through smem ----
    float* s_z = (float*)smem;
    const int gq = lane >> 2, kq = lane & 3;
    const int m0 = mt * TM;
    const size_t HC = (size_t)MTOT * UDIM;
    const int ul = tid & 31;                 // unit lane (32 units per CTA)
    const int rb = tid >> 5;                 // 8 row blocks of 16 rows
    const int u = nt * 32 + ul;
    const float bf = __ldg(bfp + u);
    const float bi = __ldg(bip + u);
    const float bo = __ldg(bop + u);
    const float bg = __ldg(bgp + u);

#pragma unroll
    for (int hf = 0; hf < 2; hf++) {
        __syncthreads();   // pipeline done / previous half consumed
        if ((wmi >> 1) == hf) {
#pragma unroll
            for (int mf = 0; mf < 4; mf++)
#pragma unroll
                for (int nf = 0; nf < 8; nf++) {
                    int row = (wmi & 1) * 64 + mf * 16 + gq;
                    int col = wni * 64 + nf * 8 + 2 * kq;
                    *(float2*)(s_z + row * ZLD + col) =
                        make_float2(acc[mf][nf][0], acc[mf][nf][1]);
                    *(float2*)(s_z + (row + 8) * ZLD + col) =
                        make_float2(acc[mf][nf][2], acc[mf][nf][3]);
                }
        }
        __syncthreads();

#pragma unroll 4
        for (int rr = 0; rr < 16; rr++) {
            int row = rb * 16 + rr;
            float4 z = *(const float4*)(s_z + row * ZLD + 4 * ul);
            size_t g = (size_t)(m0 + hf * 128 + row) * UDIM + u;
            float zf = z.x + bf, zi = z.y + bi, zo = z.z + bo, zg = z.w + bg;
            float fg = 1.f / (1.f + expf(-zf));
            float ig = 1.f / (1.f + expf(-zi));
            float og = 1.f / (1.f + expf(-zo));
            float gg = tanhf(zg);
            float cn = fg * __ldg(cin + g) + ig * gg;
            float hn = og * tanhf(cn);
            out[g] = hn;          // h_new
            out[HC + g] = cn;     // c_new
        }
    }
}

// ---------------------------------------------------------------- launch
extern "C" void kernel_launch(void* const* d_in, const int* in_sizes, int n_in,
                              void* d_out, int out_size) {
    (void)in_sizes; (void)n_in; (void)out_size;
    const float* x   = (const float*)d_in[0];
    const float* h   = (const float*)d_in[1];
    const float* c   = (const float*)d_in[2];
    const float* Wxf = (const float*)d_in[3];
    const float* Wxi = (const float*)d_in[4];
    const float* Wxo = (const float*)d_in[5];
    const float* Wxg = (const float*)d_in[6];
    const float* bf  = (const float*)d_in[7];
    const float* bi  = (const float*)d_in[8];
    const float* bo  = (const float*)d_in[9];
    const float* bg  = (const float*)d_in[10];
    const float* Whf = (const float*)d_in[11];
    const float* Whi = (const float*)d_in[12];
    const float* Who = (const float*)d_in[13];
    const float* Whg = (const float*)d_in[14];
    float* out = (float*)d_out;

    static int smem_set = 0;
    if (!smem_set) {
        cudaFuncSetAttribute(lstm_gemm_kernel,
                             cudaFuncAttributeMaxDynamicSharedMemorySize,
                             SMEM_BYTES);
        smem_set = 1;
    }

    pack_AW_kernel<<<NA_BLOCKS + NW_BLOCKS, 256>>>(
        x, h, Wxf, Wxi, Wxo, Wxg, Whf, Whi, Who, Whg);
    lstm_gemm_kernel<<<(MTOT / TM) * (NTOT / TN), NTHREADS, SMEM_BYTES>>>(
        c, bf, bi, bo, bg, out);
}